// round 1
// baseline (speedup 1.0000x reference)
#include <cuda_runtime.h>
#include <math.h>

#define NP 128
#define DD 2048
#define NN (NP*NP)   // 16384

// ---- scratch (no allocations allowed) ----
__device__ float g_part[8*NN];    // split-K partials
__device__ float g_P[NN];         // P = V G^T / n
__device__ float g_S[NN];         // S = n P P^T = V M V^T
__device__ float g_vM[NP*DD];     // vM = P G = V M
__device__ float g_kern[NN];      // exp(-dMsd/(2h))
__device__ float g_rs[NP];        // rowsum(kern)/h
__device__ float g_h[2];          // [0]=1/(2h), [1]=1/h

// ============================================================
// C_part[bz] = A[128,K] slice(bz) dot B[128,K] slice(bz), row-row dots.
// block(16,16), each thread 2x2 outputs; grid (4,4,nz).
// ============================================================
__global__ void dot_nt_partial(const float* __restrict__ A,
                               const float* __restrict__ B,
                               float* __restrict__ Cpart,
                               int K, int kslice)
{
    __shared__ float4 As[32][17];
    __shared__ float4 Bs[32][17];
    int tx = threadIdx.x, ty = threadIdx.y;
    int tid = ty*16 + tx;
    int K4 = K >> 2;
    int kbase4 = (blockIdx.z * kslice) >> 2;
    const float4* A4 = (const float4*)A;
    const float4* B4 = (const float4*)B;
    int arow0 = blockIdx.y * 32;
    int brow0 = blockIdx.x * 32;

    float a00=0.f, a01=0.f, a10=0.f, a11=0.f;

    for (int c0 = 0; c0 < kslice; c0 += 64) {
        int q0 = kbase4 + (c0 >> 2);
        #pragma unroll
        for (int t = 0; t < 2; t++) {
            int idx = tid + t*256;
            int r = idx >> 4, q = idx & 15;
            As[r][q] = A4[(arow0 + r)*K4 + q0 + q];
            Bs[r][q] = B4[(brow0 + r)*K4 + q0 + q];
        }
        __syncthreads();
        #pragma unroll
        for (int q = 0; q < 16; q++) {
            float4 av0 = As[2*ty  ][q];
            float4 av1 = As[2*ty+1][q];
            float4 bv0 = Bs[2*tx  ][q];
            float4 bv1 = Bs[2*tx+1][q];
            a00 += av0.x*bv0.x + av0.y*bv0.y + av0.z*bv0.z + av0.w*bv0.w;
            a01 += av0.x*bv1.x + av0.y*bv1.y + av0.z*bv1.z + av0.w*bv1.w;
            a10 += av1.x*bv0.x + av1.y*bv0.y + av1.z*bv0.z + av1.w*bv0.w;
            a11 += av1.x*bv1.x + av1.y*bv1.y + av1.z*bv1.z + av1.w*bv1.w;
        }
        __syncthreads();
    }
    float* Cz = Cpart + blockIdx.z * NN;
    int r0 = arow0 + 2*ty, c0o = brow0 + 2*tx;
    Cz[ r0   *NP + c0o    ] = a00;
    Cz[ r0   *NP + c0o + 1] = a01;
    Cz[(r0+1)*NP + c0o    ] = a10;
    Cz[(r0+1)*NP + c0o + 1] = a11;
}

__global__ void reduce_partials(const float* __restrict__ part,
                                float* __restrict__ C, int nz, float scale)
{
    int idx = blockIdx.x*256 + threadIdx.x;
    float s = 0.f;
    for (int z = 0; z < nz; z++) s += part[z*NN + idx];
    C[idx] = s * scale;
}

// ============================================================
// vM = P[128,128] @ G[128,2048]. block 128 threads (one col each),
// 16 rows per thread; grid (16, 8).
// ============================================================
__global__ void gemm_vM(const float* __restrict__ G)
{
    __shared__ float4 Ps[16][32];
    int tid = threadIdx.x;
    int c  = blockIdx.x*128 + tid;
    int i0 = blockIdx.y*16;
    const float4* P4 = (const float4*)g_P;
    for (int idx = tid; idx < 512; idx += 128)
        Ps[idx>>5][idx&31] = P4[(i0 + (idx>>5))*32 + (idx&31)];
    __syncthreads();

    float acc[16];
    #pragma unroll
    for (int r = 0; r < 16; r++) acc[r] = 0.f;

    for (int j4 = 0; j4 < 32; j4++) {
        int j = 4*j4;
        float b0 = G[(j  )*DD + c];
        float b1 = G[(j+1)*DD + c];
        float b2 = G[(j+2)*DD + c];
        float b3 = G[(j+3)*DD + c];
        #pragma unroll
        for (int r = 0; r < 16; r++) {
            float4 p = Ps[r][j4];
            acc[r] += p.x*b0 + p.y*b1 + p.z*b2 + p.w*b3;
        }
    }
    #pragma unroll
    for (int r = 0; r < 16; r++) g_vM[(i0+r)*DD + c] = acc[r];
}

// ============================================================
// Median via 4-pass radix select over dMsd(i,j) computed on the fly.
// rank 8192 (0-based) of 16384; writes 1/(2h), 1/h.
// ============================================================
__global__ void median_kernel()
{
    __shared__ unsigned hist[256];
    __shared__ unsigned sh_prefix;
    __shared__ int sh_k;
    int tid = threadIdx.x;
    if (tid == 0) { sh_prefix = 0u; sh_k = 8192; }

    for (int shift = 24; shift >= 0; shift -= 8) {
        hist[tid] = 0u;
        __syncthreads();
        unsigned pref = sh_prefix;
        for (int idx = tid; idx < NN; idx += 256) {
            int i = idx >> 7, j = idx & 127;
            float d = g_S[i*NP+i] + g_S[j*NP+j] - g_S[i*NP+j] - g_S[j*NP+i];
            unsigned u = __float_as_uint(d);
            unsigned key = (u & 0x80000000u) ? ~u : (u | 0x80000000u);
            if (shift == 24 || (key >> (shift+8)) == pref)
                atomicAdd(&hist[(key >> shift) & 255], 1u);
        }
        __syncthreads();
        if (tid == 0) {
            unsigned k = (unsigned)sh_k, cum = 0u; int b = 0;
            for (; b < 256; b++) {
                unsigned hh = hist[b];
                if (cum + hh > k) break;
                cum += hh;
            }
            sh_k = (int)(k - cum);
            sh_prefix = (sh_prefix << 8) | (unsigned)b;
        }
        __syncthreads();
    }
    if (tid == 0) {
        unsigned key = sh_prefix;
        unsigned u = (key & 0x80000000u) ? (key ^ 0x80000000u) : ~key;
        float med = __uint_as_float(u);
        float h = (med * med) / 6.9314718f;   // ln(128) as fp32
        g_h[0] = 0.5f / h;
        g_h[1] = 1.0f / h;
    }
}

// ============================================================
// kern + rowsum/h. one block per row i.
// ============================================================
__global__ void kern_rs_kernel()
{
    __shared__ float red[128];
    int i = blockIdx.x, j = threadIdx.x;
    float inv2h = g_h[0];
    float d = g_S[i*NP+i] + g_S[j*NP+j] - g_S[i*NP+j] - g_S[j*NP+i];
    float kv = expf(-d * inv2h);
    g_kern[i*NP + j] = kv;
    red[j] = kv;
    __syncthreads();
    for (int s = 64; s > 0; s >>= 1) {
        if (j < s) red[j] += red[j + s];
        __syncthreads();
    }
    if (j == 0) g_rs[i] = red[0] * g_h[1];
}

// ============================================================
// out = kern@G + (kern@vM)/h - rs[i]*vM[i,:].  grid (16,8), block 128.
// ============================================================
__global__ void final_kernel(const float* __restrict__ G, float* __restrict__ out)
{
    __shared__ float4 Ks[16][32];
    int tid = threadIdx.x;
    int c  = blockIdx.x*128 + tid;
    int i0 = blockIdx.y*16;
    const float4* K4 = (const float4*)g_kern;
    for (int idx = tid; idx < 512; idx += 128)
        Ks[idx>>5][idx&31] = K4[(i0 + (idx>>5))*32 + (idx&31)];
    __syncthreads();

    float ag[16], av[16];
    #pragma unroll
    for (int r = 0; r < 16; r++) { ag[r] = 0.f; av[r] = 0.f; }

    for (int j4 = 0; j4 < 32; j4++) {
        int j = 4*j4;
        float gb0 = G[(j  )*DD + c];
        float gb1 = G[(j+1)*DD + c];
        float gb2 = G[(j+2)*DD + c];
        float gb3 = G[(j+3)*DD + c];
        float vb0 = g_vM[(j  )*DD + c];
        float vb1 = g_vM[(j+1)*DD + c];
        float vb2 = g_vM[(j+2)*DD + c];
        float vb3 = g_vM[(j+3)*DD + c];
        #pragma unroll
        for (int r = 0; r < 16; r++) {
            float4 kq = Ks[r][j4];
            ag[r] += kq.x*gb0 + kq.y*gb1 + kq.z*gb2 + kq.w*gb3;
            av[r] += kq.x*vb0 + kq.y*vb1 + kq.z*vb2 + kq.w*vb3;
        }
    }
    float inv_h = g_h[1];
    #pragma unroll
    for (int r = 0; r < 16; r++) {
        int i = i0 + r;
        out[i*DD + c] = ag[r] + inv_h*av[r] - g_rs[i]*g_vM[i*DD + c];
    }
}

extern "C" void kernel_launch(void* const* d_in, const int* in_sizes, int n_in,
                              void* d_out, int out_size)
{
    const float* var  = (const float*)d_in[0];
    const float* grad = (const float*)d_in[1];
    float* out = (float*)d_out;

    float *pP = nullptr, *pPart = nullptr, *pS = nullptr;
    cudaGetSymbolAddress((void**)&pP,    g_P);
    cudaGetSymbolAddress((void**)&pPart, g_part);
    cudaGetSymbolAddress((void**)&pS,    g_S);

    // P = V G^T / n   (K=2048, split-K x8)
    dot_nt_partial<<<dim3(4,4,8), dim3(16,16)>>>(var, grad, pPart, 2048, 256);
    reduce_partials<<<64,256>>>(pPart, pP, 8, 1.0f/128.0f);

    // S = n * P P^T   (K=128)
    dot_nt_partial<<<dim3(4,4,1), dim3(16,16)>>>(pP, pP, pPart, 128, 128);
    reduce_partials<<<64,256>>>(pPart, pS, 1, 128.0f);

    // vM = P G
    gemm_vM<<<dim3(16,8),128>>>(grad);

    // median -> h ; kern + rowsums ; final output
    median_kernel<<<1,256>>>();
    kern_rs_kernel<<<128,128>>>();
    final_kernel<<<dim3(16,8),128>>>(grad, out);
}